// round 2
// baseline (speedup 1.0000x reference)
#include <cuda_runtime.h>
#include <math.h>

#define BB 2
#define SS 2048
#define DD 1024
#define HH 16
#define DK 64
#define M_TOT (BB*SS)

// Scratch (allocation rules: __device__ globals only)
__device__ float g_q[(size_t)BB*HH*SS*DK];     // [B,H,S,dk]
__device__ float g_k[(size_t)BB*HH*SS*DK];
__device__ float g_v[(size_t)BB*HH*SS*DK];
__device__ float g_attn[(size_t)BB*SS*DD];     // [B,S,D]

__device__ __forceinline__ unsigned f2tf32(float x) {
    unsigned r;
    asm("cvt.rna.tf32.f32 %0, %1;" : "=r"(r) : "f"(x));
    return r;
}

__device__ __forceinline__ void mma_tf32(float c[4],
                                         const unsigned a[4],
                                         const unsigned b[2]) {
    asm volatile(
        "mma.sync.aligned.m16n8k8.row.col.f32.tf32.tf32.f32 "
        "{%0,%1,%2,%3}, {%4,%5,%6,%7}, {%8,%9}, {%0,%1,%2,%3};\n"
        : "+f"(c[0]), "+f"(c[1]), "+f"(c[2]), "+f"(c[3])
        : "r"(a[0]), "r"(a[1]), "r"(a[2]), "r"(a[3]),
          "r"(b[0]), "r"(b[1]));
}

// ---------------------------------------------------------------------------
// tf32 tensor-core projection GEMM: out = x @ w^T
//   x: [M,1024] row-major, w: [N,1024] row-major
// MODE 0: plain store out[m*D + n]                      (output projection)
// MODE 1: permuted store out[((b*H+h)*S+s)*64 + d]      (V projection)
// MODE 2: permuted store + RoPE                         (Q/K projections)
// CTA tile 128x64xK32, 256 threads = 8 warps in 4(M) x 2(N), warp tile 32x32.
// ---------------------------------------------------------------------------
template<int MODE>
__global__ __launch_bounds__(256)
void proj_tc(const float* __restrict__ x, const float* __restrict__ w,
             const int* __restrict__ tp, float* __restrict__ out)
{
    __shared__ unsigned As[128][36];   // [m][k] tf32 bits, pitch 36 (144B, 16B-aligned)
    __shared__ unsigned Ws[64][36];    // [n][k] tf32 bits

    const int tid  = threadIdx.x;
    const int lane = tid & 31;
    const int wid  = tid >> 5;
    const int g    = lane >> 2;        // group id 0..7
    const int t    = lane & 3;         // thread-in-group 0..3
    const int wm   = wid >> 1;         // warp row 0..3
    const int wn   = wid & 1;          // warp col 0..1
    const int m0   = blockIdx.y * 128;
    const int n0   = blockIdx.x * 64;

    float acc[2][4][4] = {};           // [m-atom][n-atom][frag]

    for (int k0 = 0; k0 < DD; k0 += 32) {
        // ---- load A tile (128x32) : 4 float4 per thread ----
#pragma unroll
        for (int p = 0; p < 4; p++) {
            const int v = tid + p * 256;           // 0..1023
            const int row = v >> 3, cs = (v & 7) * 4;
            float4 a = *(const float4*)(x + (size_t)(m0 + row) * DD + k0 + cs);
            uint4 u = make_uint4(f2tf32(a.x), f2tf32(a.y), f2tf32(a.z), f2tf32(a.w));
            *(uint4*)&As[row][cs] = u;
        }
        // ---- load W tile (64x32) : 2 float4 per thread ----
#pragma unroll
        for (int p = 0; p < 2; p++) {
            const int v = tid + p * 256;           // 0..511
            const int row = v >> 3, cs = (v & 7) * 4;
            float4 a = *(const float4*)(w + (size_t)(n0 + row) * DD + k0 + cs);
            uint4 u = make_uint4(f2tf32(a.x), f2tf32(a.y), f2tf32(a.z), f2tf32(a.w));
            *(uint4*)&Ws[row][cs] = u;
        }
        __syncthreads();

#pragma unroll
        for (int kk = 0; kk < 32; kk += 8) {
            unsigned af[2][4], bf[4][2];
#pragma unroll
            for (int i = 0; i < 2; i++) {
                const int rb = wm * 32 + i * 16;
                af[i][0] = As[rb + g    ][kk + t    ];
                af[i][1] = As[rb + g + 8][kk + t    ];
                af[i][2] = As[rb + g    ][kk + t + 4];
                af[i][3] = As[rb + g + 8][kk + t + 4];
            }
#pragma unroll
            for (int j = 0; j < 4; j++) {
                const int nb = wn * 32 + j * 8;
                bf[j][0] = Ws[nb + g][kk + t    ];
                bf[j][1] = Ws[nb + g][kk + t + 4];
            }
#pragma unroll
            for (int i = 0; i < 2; i++)
#pragma unroll
                for (int j = 0; j < 4; j++)
                    mma_tf32(acc[i][j], af[i], bf[j]);
        }
        __syncthreads();
    }

    // ---- epilogue ----
#pragma unroll
    for (int i = 0; i < 2; i++) {
        const int row0 = m0 + wm * 32 + i * 16 + g;
        const int row1 = row0 + 8;
#pragma unroll
        for (int j = 0; j < 4; j++) {
            const int col = n0 + wn * 32 + j * 8 + 2 * t;   // even
            float v00 = acc[i][j][0], v01 = acc[i][j][1];   // row0, (col, col+1)
            float v10 = acc[i][j][2], v11 = acc[i][j][3];   // row1, (col, col+1)
            if (MODE == 0) {
                *(float2*)(out + (size_t)row0 * DD + col) = make_float2(v00, v01);
                *(float2*)(out + (size_t)row1 * DD + col) = make_float2(v10, v11);
            } else {
                const int h = col >> 6, d = col & 63;        // d even
                if (MODE == 2) {
                    // freq = 10000^(-d/64), computed in double (exact to fp32 ulp),
                    // angles through accurate sincosf range reduction.
                    const float fr = (float)exp2(-(double)d * 0.20762050593046014);
                    float s0, c0, s1, c1;
                    sincosf((float)tp[row0] * fr, &s0, &c0);
                    sincosf((float)tp[row1] * fr, &s1, &c1);
                    const float e0 = v00, o0 = v01, e1 = v10, o1 = v11;
                    v00 = e0 * c0 - o0 * s0;
                    v01 = e0 * s0 + o0 * c0;
                    v10 = e1 * c1 - o1 * s1;
                    v11 = e1 * s1 + o1 * c1;
                }
                {
                    const int b0i = row0 / SS, s0i = row0 % SS;
                    *(float2*)(out + ((size_t)(b0i * HH + h) * SS + s0i) * DK + d) =
                        make_float2(v00, v01);
                }
                {
                    const int b1i = row1 / SS, s1i = row1 % SS;
                    *(float2*)(out + ((size_t)(b1i * HH + h) * SS + s1i) * DK + d) =
                        make_float2(v10, v11);
                }
            }
        }
    }
}

// ---------------------------------------------------------------------------
// Flash attention, causal. Q/K/V in [B,H,S,64]. Output to [B,S,D] scratch.
// Block: 256 threads, 64 q-rows x 64 keys per tile, online softmax. (fp32)
// ---------------------------------------------------------------------------
__global__ __launch_bounds__(256)
void attn_kernel(const float* __restrict__ Q, const float* __restrict__ K,
                 const float* __restrict__ V, float* __restrict__ O)
{
    extern __shared__ float sm[];
    float* Qs = sm;              // [d][r]  stride 68
    float* Ks = Qs + 64*68;      // [d][c]  stride 68
    float* Vs = Ks + 64*68;      // [c][d]  stride 68 (natural)
    float* Ps = Vs + 64*68;      // [c][r]  stride 68

    const int tid = threadIdx.x;
    const int txi = tid & 15, tyi = tid >> 4;
    const int qt = blockIdx.x, h = blockIdx.y, b = blockIdx.z;
    const size_t headoff = (size_t)(b*HH + h) * SS * DK;
    const float* Qb = Q + headoff + (size_t)qt * 64 * DK;
    const float* Kb = K + headoff;
    const float* Vb = V + headoff;

    const int ldrow = tid >> 2;            // 0..63
    const int ldcb  = (tid & 3) * 16;      // column base, 16 floats per thread

    // Load Q tile transposed [d][r]
#pragma unroll
    for (int ss = 0; ss < 16; ss += 4) {
        const int dc = ldcb + ss;
        float4 qv = *(const float4*)(Qb + ldrow*DK + dc);
        Qs[(dc+0)*68 + ldrow] = qv.x;
        Qs[(dc+1)*68 + ldrow] = qv.y;
        Qs[(dc+2)*68 + ldrow] = qv.z;
        Qs[(dc+3)*68 + ldrow] = qv.w;
    }
    __syncthreads();

    float o[4][4] = {};
    float m_st[4], l_st[4];
#pragma unroll
    for (int i = 0; i < 4; i++) { m_st[i] = -INFINITY; l_st[i] = 0.0f; }

    for (int kt = 0; kt <= qt; kt++) {
        const float* Kt = Kb + (size_t)kt * 64 * DK;
        const float* Vt = Vb + (size_t)kt * 64 * DK;
#pragma unroll
        for (int ss = 0; ss < 16; ss += 4) {
            const int dc = ldcb + ss;
            float4 kv = *(const float4*)(Kt + ldrow*DK + dc);
            Ks[(dc+0)*68 + ldrow] = kv.x;
            Ks[(dc+1)*68 + ldrow] = kv.y;
            Ks[(dc+2)*68 + ldrow] = kv.z;
            Ks[(dc+3)*68 + ldrow] = kv.w;
            float4 vv = *(const float4*)(Vt + ldrow*DK + dc);
            *(float4*)&Vs[ldrow*68 + dc] = vv;
        }
        __syncthreads();

        // S = Q K^T over d=64
        float sc[4][4] = {};
#pragma unroll 8
        for (int dd = 0; dd < 64; dd++) {
            float4 a  = *(const float4*)&Qs[dd*68 + 4*tyi];
            float4 bv = *(const float4*)&Ks[dd*68 + 4*txi];
            float ar[4] = {a.x, a.y, a.z, a.w};
            float br[4] = {bv.x, bv.y, bv.z, bv.w};
#pragma unroll
            for (int i = 0; i < 4; i++)
#pragma unroll
                for (int j = 0; j < 4; j++)
                    sc[i][j] += ar[i] * br[j];
        }

        if (kt == qt) {
#pragma unroll
            for (int i = 0; i < 4; i++)
#pragma unroll
                for (int j = 0; j < 4; j++)
                    if (4*txi + j > 4*tyi + i) sc[i][j] = -INFINITY;
        }

        // online softmax per row (row group = 16 lanes sharing tyi = half warp)
#pragma unroll
        for (int i = 0; i < 4; i++) {
            float mx = -INFINITY;
#pragma unroll
            for (int j = 0; j < 4; j++) {
                sc[i][j] *= 0.125f;            // 1/sqrt(64); -inf stays -inf
                mx = fmaxf(mx, sc[i][j]);
            }
#pragma unroll
            for (int off = 8; off >= 1; off >>= 1)
                mx = fmaxf(mx, __shfl_xor_sync(0xffffffffu, mx, off, 16));
            const float mnew = fmaxf(m_st[i], mx);
            const float corr = __expf(m_st[i] - mnew);
            float rs = 0.0f;
#pragma unroll
            for (int j = 0; j < 4; j++) {
                const float p = __expf(sc[i][j] - mnew);
                sc[i][j] = p;
                rs += p;
            }
#pragma unroll
            for (int off = 8; off >= 1; off >>= 1)
                rs += __shfl_xor_sync(0xffffffffu, rs, off, 16);
            l_st[i] = l_st[i] * corr + rs;
            m_st[i] = mnew;
#pragma unroll
            for (int j = 0; j < 4; j++) o[i][j] *= corr;
        }

        // stage P transposed [c][r]
#pragma unroll
        for (int i = 0; i < 4; i++)
#pragma unroll
            for (int j = 0; j < 4; j++)
                Ps[(4*txi + j)*68 + 4*tyi + i] = sc[i][j];
        __syncthreads();

        // O += P V over c=64
#pragma unroll 8
        for (int c = 0; c < 64; c++) {
            float4 a  = *(const float4*)&Ps[c*68 + 4*tyi];
            float4 bv = *(const float4*)&Vs[c*68 + 4*txi];
            float ar[4] = {a.x, a.y, a.z, a.w};
            float br[4] = {bv.x, bv.y, bv.z, bv.w};
#pragma unroll
            for (int i = 0; i < 4; i++)
#pragma unroll
                for (int j = 0; j < 4; j++)
                    o[i][j] += ar[i] * br[j];
        }
        __syncthreads();
    }

    // epilogue: normalize, store to [B,S,D]
#pragma unroll
    for (int i = 0; i < 4; i++) {
        const float inv = 1.0f / l_st[i];
        const int srow = qt*64 + 4*tyi + i;
        *(float4*)(O + ((size_t)b*SS + srow) * DD + h*DK + 4*txi) =
            make_float4(o[i][0]*inv, o[i][1]*inv, o[i][2]*inv, o[i][3]*inv);
    }
}

// ---------------------------------------------------------------------------
extern "C" void kernel_launch(void* const* d_in, const int* in_sizes, int n_in,
                              void* d_out, int out_size)
{
    const float* x  = (const float*)d_in[0];
    const int*   tp = (const int*)  d_in[1];
    const float* wq = (const float*)d_in[2];
    const float* wk = (const float*)d_in[3];
    const float* wv = (const float*)d_in[4];
    const float* wo = (const float*)d_in[5];
    float* out = (float*)d_out;

    float *q, *k, *v, *attn;
    cudaGetSymbolAddress((void**)&q,    g_q);
    cudaGetSymbolAddress((void**)&k,    g_k);
    cudaGetSymbolAddress((void**)&v,    g_v);
    cudaGetSymbolAddress((void**)&attn, g_attn);

    const dim3 pgrid(DD/64, M_TOT/128);   // (16, 32)

    proj_tc<2><<<pgrid, 256>>>(x, wq, tp, q);
    proj_tc<2><<<pgrid, 256>>>(x, wk, tp, k);
    proj_tc<1><<<pgrid, 256>>>(x, wv, tp, v);

    const size_t smem = 4 * 64 * 68 * sizeof(float);   // 69632 B
    cudaFuncSetAttribute(attn_kernel,
                         cudaFuncAttributeMaxDynamicSharedMemorySize, (int)smem);
    attn_kernel<<<dim3(SS/64, HH, BB), 256, smem>>>(q, k, v, attn);

    proj_tc<0><<<pgrid, 256>>>(attn, wo, tp, out);
}

// round 3
// speedup vs baseline: 1.5937x; 1.5937x over previous
#include <cuda_runtime.h>
#include <math.h>

#define BB 2
#define SS 2048
#define DD 1024
#define HH 16
#define DK 64
#define M_TOT (BB*SS)
#define PH 72            // smem pitch in halves (144B rows, conflict-free)

typedef unsigned short ushort_t;

// Scratch (__device__ globals only; 16B-aligned for vector ld/st)
__device__ __align__(16) ushort_t g_qh[(size_t)BB*HH*SS*DK];
__device__ __align__(16) ushort_t g_ql[(size_t)BB*HH*SS*DK];
__device__ __align__(16) ushort_t g_kh[(size_t)BB*HH*SS*DK];
__device__ __align__(16) ushort_t g_kl[(size_t)BB*HH*SS*DK];
__device__ __align__(16) ushort_t g_vh[(size_t)BB*HH*SS*DK];
__device__ __align__(16) ushort_t g_vl[(size_t)BB*HH*SS*DK];
__device__ __align__(16) float    g_attn[(size_t)BB*SS*DD];

// ---------------------------------------------------------------------------
// helpers
// ---------------------------------------------------------------------------
__device__ __forceinline__ unsigned f2tf32(float x) {
    unsigned r; asm("cvt.rna.tf32.f32 %0, %1;" : "=r"(r) : "f"(x)); return r;
}
__device__ __forceinline__ void mma_tf32(float c[4], const unsigned a[4], const unsigned b[2]) {
    asm volatile(
        "mma.sync.aligned.m16n8k8.row.col.f32.tf32.tf32.f32 "
        "{%0,%1,%2,%3}, {%4,%5,%6,%7}, {%8,%9}, {%0,%1,%2,%3};\n"
        : "+f"(c[0]), "+f"(c[1]), "+f"(c[2]), "+f"(c[3])
        : "r"(a[0]), "r"(a[1]), "r"(a[2]), "r"(a[3]), "r"(b[0]), "r"(b[1]));
}
__device__ __forceinline__ void mma_bf16(float c[4], const unsigned a[4],
                                         unsigned b0, unsigned b1) {
    asm volatile(
        "mma.sync.aligned.m16n8k16.row.col.f32.bf16.bf16.f32 "
        "{%0,%1,%2,%3}, {%4,%5,%6,%7}, {%8,%9}, {%0,%1,%2,%3};\n"
        : "+f"(c[0]), "+f"(c[1]), "+f"(c[2]), "+f"(c[3])
        : "r"(a[0]), "r"(a[1]), "r"(a[2]), "r"(a[3]), "r"(b0), "r"(b1));
}
__device__ __forceinline__ unsigned su32(const void* p) {
    return (unsigned)__cvta_generic_to_shared(p);
}
__device__ __forceinline__ void ldsm4(unsigned r[4], unsigned a) {
    asm volatile("ldmatrix.sync.aligned.m8n8.x4.shared.b16 {%0,%1,%2,%3}, [%4];"
        : "=r"(r[0]), "=r"(r[1]), "=r"(r[2]), "=r"(r[3]) : "r"(a));
}
__device__ __forceinline__ void ldsm4t(unsigned r[4], unsigned a) {
    asm volatile("ldmatrix.sync.aligned.m8n8.x4.trans.shared.b16 {%0,%1,%2,%3}, [%4];"
        : "=r"(r[0]), "=r"(r[1]), "=r"(r[2]), "=r"(r[3]) : "r"(a));
}
__device__ __forceinline__ float ex2(float x) {
    float y; asm("ex2.approx.f32 %0, %1;" : "=f"(y) : "f"(x)); return y;
}
// pack (v0 -> low half, v1 -> high half) into bf16x2; also produce residual pack
__device__ __forceinline__ void pack_split(unsigned &hi, unsigned &lo, float v0, float v1) {
    asm("cvt.rn.bf16x2.f32 %0, %1, %2;" : "=r"(hi) : "f"(v1), "f"(v0));
    const float h0 = __uint_as_float(hi << 16);
    const float h1 = __uint_as_float(hi & 0xffff0000u);
    asm("cvt.rn.bf16x2.f32 %0, %1, %2;" : "=r"(lo) : "f"(v1 - h1), "f"(v0 - h0));
}

// ---------------------------------------------------------------------------
// tf32 tensor-core projection GEMM: out = x @ w^T
// MODE 0: fp32 store out[m*D+n]                               (wo)
// MODE 1: bf16 hi/lo split store [b,h,s,d]                    (V)
// MODE 2: RoPE + scale, bf16 hi/lo split store [b,h,s,d]      (Q: scale=.125*log2e, K: 1)
// CTA tile 128x64xK32, 256 thr, warp tile 32x32.
// ---------------------------------------------------------------------------
template<int MODE>
__global__ __launch_bounds__(256)
void proj_tc(const float* __restrict__ x, const float* __restrict__ w,
             const int* __restrict__ tp, float* __restrict__ outf,
             ushort_t* __restrict__ oh, ushort_t* __restrict__ ol, float scale)
{
    __shared__ unsigned As[128][36];
    __shared__ unsigned Ws[64][36];

    const int tid  = threadIdx.x;
    const int lane = tid & 31;
    const int wid  = tid >> 5;
    const int g    = lane >> 2;
    const int t    = lane & 3;
    const int wm   = wid >> 1;
    const int wn   = wid & 1;
    const int m0   = blockIdx.y * 128;
    const int n0   = blockIdx.x * 64;

    float acc[2][4][4] = {};

    for (int k0 = 0; k0 < DD; k0 += 32) {
#pragma unroll
        for (int p = 0; p < 4; p++) {
            const int v = tid + p * 256;
            const int row = v >> 3, cs = (v & 7) * 4;
            float4 a = *(const float4*)(x + (size_t)(m0 + row) * DD + k0 + cs);
            *(uint4*)&As[row][cs] = make_uint4(f2tf32(a.x), f2tf32(a.y), f2tf32(a.z), f2tf32(a.w));
        }
#pragma unroll
        for (int p = 0; p < 2; p++) {
            const int v = tid + p * 256;
            const int row = v >> 3, cs = (v & 7) * 4;
            float4 a = *(const float4*)(w + (size_t)(n0 + row) * DD + k0 + cs);
            *(uint4*)&Ws[row][cs] = make_uint4(f2tf32(a.x), f2tf32(a.y), f2tf32(a.z), f2tf32(a.w));
        }
        __syncthreads();

#pragma unroll
        for (int kk = 0; kk < 32; kk += 8) {
            unsigned af[2][4], bf[4][2];
#pragma unroll
            for (int i = 0; i < 2; i++) {
                const int rb = wm * 32 + i * 16;
                af[i][0] = As[rb + g    ][kk + t    ];
                af[i][1] = As[rb + g + 8][kk + t    ];
                af[i][2] = As[rb + g    ][kk + t + 4];
                af[i][3] = As[rb + g + 8][kk + t + 4];
            }
#pragma unroll
            for (int j = 0; j < 4; j++) {
                const int nb = wn * 32 + j * 8;
                bf[j][0] = Ws[nb + g][kk + t    ];
                bf[j][1] = Ws[nb + g][kk + t + 4];
            }
#pragma unroll
            for (int i = 0; i < 2; i++)
#pragma unroll
                for (int j = 0; j < 4; j++)
                    mma_tf32(acc[i][j], af[i], bf[j]);
        }
        __syncthreads();
    }

#pragma unroll
    for (int i = 0; i < 2; i++) {
        const int row0 = m0 + wm * 32 + i * 16 + g;
        const int row1 = row0 + 8;
#pragma unroll
        for (int j = 0; j < 4; j++) {
            const int col = n0 + wn * 32 + j * 8 + 2 * t;   // even
            float v00 = acc[i][j][0], v01 = acc[i][j][1];
            float v10 = acc[i][j][2], v11 = acc[i][j][3];
            if (MODE == 0) {
                *(float2*)(outf + (size_t)row0 * DD + col) = make_float2(v00, v01);
                *(float2*)(outf + (size_t)row1 * DD + col) = make_float2(v10, v11);
            } else {
                const int h = col >> 6, d = col & 63;       // d even
                if (MODE == 2) {
                    const float fr = (float)exp2(-(double)d * 0.20762050593046014);
                    float s0, c0, s1, c1;
                    sincosf((float)tp[row0] * fr, &s0, &c0);
                    sincosf((float)tp[row1] * fr, &s1, &c1);
                    const float e0 = v00, o0 = v01, e1 = v10, o1 = v11;
                    v00 = (e0 * c0 - o0 * s0) * scale;
                    v01 = (e0 * s0 + o0 * c0) * scale;
                    v10 = (e1 * c1 - o1 * s1) * scale;
                    v11 = (e1 * s1 + o1 * c1) * scale;
                }
                unsigned ph, pl;
                {
                    const int bb = row0 / SS, s = row0 % SS;
                    const size_t pidx = (((size_t)(bb * HH + h) * SS + s) * DK + d) >> 1;
                    pack_split(ph, pl, v00, v01);
                    ((unsigned*)oh)[pidx] = ph;
                    ((unsigned*)ol)[pidx] = pl;
                }
                {
                    const int bb = row1 / SS, s = row1 % SS;
                    const size_t pidx = (((size_t)(bb * HH + h) * SS + s) * DK + d) >> 1;
                    pack_split(ph, pl, v10, v11);
                    ((unsigned*)oh)[pidx] = ph;
                    ((unsigned*)ol)[pidx] = pl;
                }
            }
        }
    }
}

// ---------------------------------------------------------------------------
// Tensor-core causal flash attention, bf16x3 (near-fp32 accuracy).
// CTA: 128 q-rows, 256 thr (8 warps x 16 rows). K-tiles of 64.
// Scores arrive pre-scaled by 0.125*log2e -> softmax in exp2 domain.
// ---------------------------------------------------------------------------
__global__ __launch_bounds__(256)
void attn_tc(const ushort_t* __restrict__ Qhg, const ushort_t* __restrict__ Qlg,
             const ushort_t* __restrict__ Khg, const ushort_t* __restrict__ Klg,
             const ushort_t* __restrict__ Vhg, const ushort_t* __restrict__ Vlg,
             float* __restrict__ O)
{
    extern __shared__ ushort_t smem_us[];
    ushort_t* Qh = smem_us;            // 128*PH
    ushort_t* Ql = Qh + 128 * PH;
    ushort_t* Kh = Ql + 128 * PH;      // 64*PH each below
    ushort_t* Kl = Kh + 64 * PH;
    ushort_t* Vh = Kl + 64 * PH;
    ushort_t* Vl = Vh + 64 * PH;

    const int tid  = threadIdx.x;
    const int lane = tid & 31, wid = tid >> 5;
    const int g = lane >> 2, t = lane & 3;
    const int qt = (int)gridDim.x - 1 - (int)blockIdx.x;  // heavy CTAs first
    const int h = blockIdx.y, b = blockIdx.z;
    const int Q0 = qt * 128;
    const size_t hoff = (size_t)(b * HH + h) * SS * DK;

    // ldmatrix lane-address components
    const int grp = lane >> 3, li = lane & 7;
    const int a_r = (grp & 1) * 8 + li, a_c = (grp >> 1) * 8;   // A-frag (and V-trans)
    const int b_r = (grp >> 1) * 8 + li, b_c = (grp & 1) * 8;   // B-frag (K)

    // ---- load Q tile (128 rows, hi+lo) ----
    {
        const int row = tid & 63, cq = tid >> 6;
#pragma unroll
        for (int rr = 0; rr < 128; rr += 64)
#pragma unroll
            for (int cc = 0; cc < 8; cc += 4) {
                const int r = row + rr, c8 = (cq + cc) * 8;
                const size_t gsrc = hoff + (size_t)(Q0 + r) * DK + c8;
                *(uint4*)&Qh[r * PH + c8] = *(const uint4*)&Qhg[gsrc];
                *(uint4*)&Ql[r * PH + c8] = *(const uint4*)&Qlg[gsrc];
            }
    }

    float o[8][4] = {};
    float m0 = -INFINITY, m1 = -INFINITY, l0 = 0.f, l1 = 0.f;
    const int rminl = wid * 16;
    const int rming = Q0 + rminl;

    const int ktmax = 2 * qt + 1;
    for (int kt = 0; kt <= ktmax; kt++) {
        const int C0 = kt * 64;
        __syncthreads();                      // prev-iter smem reads done
        {
            const int row = tid & 63, cq = tid >> 6;
#pragma unroll
            for (int cc = 0; cc < 8; cc += 4) {
                const int c8 = (cq + cc) * 8;
                const size_t gsrc = hoff + (size_t)(C0 + row) * DK + c8;
                *(uint4*)&Kh[row * PH + c8] = *(const uint4*)&Khg[gsrc];
                *(uint4*)&Kl[row * PH + c8] = *(const uint4*)&Klg[gsrc];
                *(uint4*)&Vh[row * PH + c8] = *(const uint4*)&Vhg[gsrc];
                *(uint4*)&Vl[row * PH + c8] = *(const uint4*)&Vlg[gsrc];
            }
        }
        __syncthreads();
        if (C0 >= rming + 16) continue;       // tile fully masked for this warp

        // ---- S = Q K^T, bf16x3 ----
        float sc[8][4];
#pragma unroll
        for (int j = 0; j < 8; j++)
#pragma unroll
            for (int e = 0; e < 4; e++) sc[j][e] = 0.f;

#pragma unroll
        for (int ks = 0; ks < 4; ks++) {
            unsigned qh4[4], ql4[4];
            ldsm4(qh4, su32(&Qh[(rminl + a_r) * PH + 16 * ks + a_c]));
            ldsm4(ql4, su32(&Ql[(rminl + a_r) * PH + 16 * ks + a_c]));
#pragma unroll
            for (int np = 0; np < 4; np++) {
                unsigned kh4[4], kl4[4];
                ldsm4(kh4, su32(&Kh[(np * 16 + b_r) * PH + 16 * ks + b_c]));
                ldsm4(kl4, su32(&Kl[(np * 16 + b_r) * PH + 16 * ks + b_c]));
                mma_bf16(sc[2 * np],     qh4, kh4[0], kh4[1]);
                mma_bf16(sc[2 * np],     qh4, kl4[0], kl4[1]);
                mma_bf16(sc[2 * np],     ql4, kh4[0], kh4[1]);
                mma_bf16(sc[2 * np + 1], qh4, kh4[2], kh4[3]);
                mma_bf16(sc[2 * np + 1], qh4, kl4[2], kl4[3]);
                mma_bf16(sc[2 * np + 1], ql4, kh4[2], kh4[3]);
            }
        }

        // ---- causal mask (diag-adjacent tiles only) ----
        if (C0 + 63 > rming) {
            const int r0g = rming + g, r1g = r0g + 8;
#pragma unroll
            for (int j = 0; j < 8; j++) {
                const int cb = C0 + 8 * j + 2 * t;
                if (cb     > r0g) sc[j][0] = -INFINITY;
                if (cb + 1 > r0g) sc[j][1] = -INFINITY;
                if (cb     > r1g) sc[j][2] = -INFINITY;
                if (cb + 1 > r1g) sc[j][3] = -INFINITY;
            }
        }

        // ---- online softmax (log2 domain) ----
        float mx0 = -INFINITY, mx1 = -INFINITY;
#pragma unroll
        for (int j = 0; j < 8; j++) {
            mx0 = fmaxf(mx0, fmaxf(sc[j][0], sc[j][1]));
            mx1 = fmaxf(mx1, fmaxf(sc[j][2], sc[j][3]));
        }
        mx0 = fmaxf(mx0, __shfl_xor_sync(0xffffffffu, mx0, 1));
        mx0 = fmaxf(mx0, __shfl_xor_sync(0xffffffffu, mx0, 2));
        mx1 = fmaxf(mx1, __shfl_xor_sync(0xffffffffu, mx1, 1));
        mx1 = fmaxf(mx1, __shfl_xor_sync(0xffffffffu, mx1, 2));
        const float mn0 = fmaxf(m0, mx0), mn1 = fmaxf(m1, mx1);
        const float cr0 = ex2(m0 - mn0),  cr1 = ex2(m1 - mn1);
        float rs0 = 0.f, rs1 = 0.f;
#pragma unroll
        for (int j = 0; j < 8; j++) {
            sc[j][0] = ex2(sc[j][0] - mn0); rs0 += sc[j][0];
            sc[j][1] = ex2(sc[j][1] - mn0); rs0 += sc[j][1];
            sc[j][2] = ex2(sc[j][2] - mn1); rs1 += sc[j][2];
            sc[j][3] = ex2(sc[j][3] - mn1); rs1 += sc[j][3];
        }
        rs0 += __shfl_xor_sync(0xffffffffu, rs0, 1);
        rs0 += __shfl_xor_sync(0xffffffffu, rs0, 2);
        rs1 += __shfl_xor_sync(0xffffffffu, rs1, 1);
        rs1 += __shfl_xor_sync(0xffffffffu, rs1, 2);
        l0 = l0 * cr0 + rs0; l1 = l1 * cr1 + rs1;
        m0 = mn0; m1 = mn1;
#pragma unroll
        for (int j = 0; j < 8; j++) {
            o[j][0] *= cr0; o[j][1] *= cr0;
            o[j][2] *= cr1; o[j][3] *= cr1;
        }

        // ---- O += P V, bf16x3 (P packed in-register from accumulators) ----
#pragma unroll
        for (int cs = 0; cs < 4; cs++) {
            unsigned ph4[4], pl4[4];
            pack_split(ph4[0], pl4[0], sc[2 * cs][0],     sc[2 * cs][1]);
            pack_split(ph4[1], pl4[1], sc[2 * cs][2],     sc[2 * cs][3]);
            pack_split(ph4[2], pl4[2], sc[2 * cs + 1][0], sc[2 * cs + 1][1]);
            pack_split(ph4[3], pl4[3], sc[2 * cs + 1][2], sc[2 * cs + 1][3]);
#pragma unroll
            for (int np = 0; np < 4; np++) {
                unsigned vh4[4], vl4[4];
                ldsm4t(vh4, su32(&Vh[(cs * 16 + a_r) * PH + np * 16 + a_c]));
                ldsm4t(vl4, su32(&Vl[(cs * 16 + a_r) * PH + np * 16 + a_c]));
                mma_bf16(o[2 * np],     ph4, vh4[0], vh4[1]);
                mma_bf16(o[2 * np],     ph4, vl4[0], vl4[1]);
                mma_bf16(o[2 * np],     pl4, vh4[0], vh4[1]);
                mma_bf16(o[2 * np + 1], ph4, vh4[2], vh4[3]);
                mma_bf16(o[2 * np + 1], ph4, vl4[2], vl4[3]);
                mma_bf16(o[2 * np + 1], pl4, vh4[2], vh4[3]);
            }
        }
    }

    // ---- epilogue: normalize, store fp32 [B,S,D] ----
    const float i0 = 1.0f / l0, i1 = 1.0f / l1;
    const int r0g = Q0 + rminl + g, r1g = r0g + 8;
    float* Ob = O + (size_t)b * SS * DD + h * DK;
#pragma unroll
    for (int j = 0; j < 8; j++) {
        const int col = 8 * j + 2 * t;
        *(float2*)(Ob + (size_t)r0g * DD + col) = make_float2(o[j][0] * i0, o[j][1] * i0);
        *(float2*)(Ob + (size_t)r1g * DD + col) = make_float2(o[j][2] * i1, o[j][3] * i1);
    }
}

// ---------------------------------------------------------------------------
extern "C" void kernel_launch(void* const* d_in, const int* in_sizes, int n_in,
                              void* d_out, int out_size)
{
    const float* x  = (const float*)d_in[0];
    const int*   tp = (const int*)  d_in[1];
    const float* wq = (const float*)d_in[2];
    const float* wk = (const float*)d_in[3];
    const float* wv = (const float*)d_in[4];
    const float* wo = (const float*)d_in[5];
    float* out = (float*)d_out;

    ushort_t *qh, *ql, *kh, *kl, *vh, *vl;
    float* attn;
    cudaGetSymbolAddress((void**)&qh, g_qh);
    cudaGetSymbolAddress((void**)&ql, g_ql);
    cudaGetSymbolAddress((void**)&kh, g_kh);
    cudaGetSymbolAddress((void**)&kl, g_kl);
    cudaGetSymbolAddress((void**)&vh, g_vh);
    cudaGetSymbolAddress((void**)&vl, g_vl);
    cudaGetSymbolAddress((void**)&attn, g_attn);

    const dim3 pgrid(DD / 64, M_TOT / 128);   // (16, 32)
    const float qscale = 0.125f * 1.44269504088896340736f;  // 1/sqrt(64) * log2(e)

    proj_tc<2><<<pgrid, 256>>>(x, wq, tp, nullptr, qh, ql, qscale);
    proj_tc<2><<<pgrid, 256>>>(x, wk, tp, nullptr, kh, kl, 1.0f);
    proj_tc<1><<<pgrid, 256>>>(x, wv, tp, nullptr, vh, vl, 1.0f);

    const int smem = (128 * 2 + 64 * 4) * PH * 2;   // 73728 B
    cudaFuncSetAttribute(attn_tc, cudaFuncAttributeMaxDynamicSharedMemorySize, smem);
    attn_tc<<<dim3(SS / 128, HH, BB), 256, smem>>>(qh, ql, kh, kl, vh, vl, attn);

    proj_tc<0><<<pgrid, 256>>>(attn, wo, tp, out, nullptr, nullptr, 1.0f);
}

// round 6
// speedup vs baseline: 1.6807x; 1.0546x over previous
#include <cuda_runtime.h>
#include <math.h>

#define BB 2
#define SS 2048
#define DD 1024
#define HH 16
#define DK 64
#define M_TOT (BB*SS)
#define PH 72            // smem pitch in halves (144B rows, conflict-free)

typedef unsigned short ushort_t;

// Scratch (__device__ globals only; 16B-aligned for vector ld/st)
__device__ __align__(16) ushort_t g_qh[(size_t)BB*HH*SS*DK];
__device__ __align__(16) ushort_t g_ql[(size_t)BB*HH*SS*DK];
__device__ __align__(16) ushort_t g_kh[(size_t)BB*HH*SS*DK];
__device__ __align__(16) ushort_t g_kl[(size_t)BB*HH*SS*DK];
__device__ __align__(16) ushort_t g_vh[(size_t)BB*HH*SS*DK];
__device__ __align__(16) ushort_t g_vl[(size_t)BB*HH*SS*DK];
__device__ __align__(16) float    g_attn[(size_t)BB*SS*DD];

// ---------------------------------------------------------------------------
// helpers
// ---------------------------------------------------------------------------
__device__ __forceinline__ unsigned f2tf32(float x) {
    unsigned r; asm("cvt.rna.tf32.f32 %0, %1;" : "=r"(r) : "f"(x)); return r;
}
__device__ __forceinline__ void mma_tf32(float c[4], const unsigned a[4], const unsigned b[2]) {
    asm volatile(
        "mma.sync.aligned.m16n8k8.row.col.f32.tf32.tf32.f32 "
        "{%0,%1,%2,%3}, {%4,%5,%6,%7}, {%8,%9}, {%0,%1,%2,%3};\n"
        : "+f"(c[0]), "+f"(c[1]), "+f"(c[2]), "+f"(c[3])
        : "r"(a[0]), "r"(a[1]), "r"(a[2]), "r"(a[3]), "r"(b[0]), "r"(b[1]));
}
__device__ __forceinline__ void mma_bf16(float c[4], const unsigned a[4],
                                         unsigned b0, unsigned b1) {
    asm volatile(
        "mma.sync.aligned.m16n8k16.row.col.f32.bf16.bf16.f32 "
        "{%0,%1,%2,%3}, {%4,%5,%6,%7}, {%8,%9}, {%0,%1,%2,%3};\n"
        : "+f"(c[0]), "+f"(c[1]), "+f"(c[2]), "+f"(c[3])
        : "r"(a[0]), "r"(a[1]), "r"(a[2]), "r"(a[3]), "r"(b0), "r"(b1));
}
__device__ __forceinline__ unsigned su32(const void* p) {
    return (unsigned)__cvta_generic_to_shared(p);
}
__device__ __forceinline__ void ldsm4(unsigned r[4], unsigned a) {
    asm volatile("ldmatrix.sync.aligned.m8n8.x4.shared.b16 {%0,%1,%2,%3}, [%4];"
        : "=r"(r[0]), "=r"(r[1]), "=r"(r[2]), "=r"(r[3]) : "r"(a));
}
__device__ __forceinline__ void ldsm4t(unsigned r[4], unsigned a) {
    asm volatile("ldmatrix.sync.aligned.m8n8.x4.trans.shared.b16 {%0,%1,%2,%3}, [%4];"
        : "=r"(r[0]), "=r"(r[1]), "=r"(r[2]), "=r"(r[3]) : "r"(a));
}
__device__ __forceinline__ float ex2(float x) {
    float y; asm("ex2.approx.f32 %0, %1;" : "=f"(y) : "f"(x)); return y;
}
__device__ __forceinline__ void pack_split(unsigned &hi, unsigned &lo, float v0, float v1) {
    asm("cvt.rn.bf16x2.f32 %0, %1, %2;" : "=r"(hi) : "f"(v1), "f"(v0));
    const float h0 = __uint_as_float(hi << 16);
    const float h1 = __uint_as_float(hi & 0xffff0000u);
    asm("cvt.rn.bf16x2.f32 %0, %1, %2;" : "=r"(lo) : "f"(v1 - h1), "f"(v0 - h0));
}
__device__ __forceinline__ void cpa16(unsigned saddr, const void* g) {
    asm volatile("cp.async.cg.shared.global [%0], [%1], 16;" :: "r"(saddr), "l"(g));
}
__device__ __forceinline__ void cpa_commit() {
    asm volatile("cp.async.commit_group;");
}
template<int N> __device__ __forceinline__ void cpa_wait() {
    asm volatile("cp.async.wait_group %0;" :: "n"(N));
}

// ---------------------------------------------------------------------------
// tf32 projection GEMM, register-staged software pipeline.
// MODE 0: fp32 store out[m*D+n]                               (wo)
// MODE 1: bf16 hi/lo split store [b,h,s,d]                    (V)
// MODE 2: RoPE + scale, bf16 hi/lo split store [b,h,s,d]      (Q/K)
// CTA tile 128x64xK32, 256 thr, warp tile 32x32.
// ---------------------------------------------------------------------------
template<int MODE>
__global__ __launch_bounds__(256)
void proj_tc(const float* __restrict__ x, const float* __restrict__ w,
             const int* __restrict__ tp, float* __restrict__ outf,
             ushort_t* __restrict__ oh, ushort_t* __restrict__ ol, float scale)
{
    __shared__ unsigned As[128][36];
    __shared__ unsigned Ws[64][36];

    const int tid  = threadIdx.x;
    const int lane = tid & 31;
    const int wid  = tid >> 5;
    const int g    = lane >> 2;
    const int t    = lane & 3;
    const int wm   = wid >> 1;
    const int wn   = wid & 1;
    const int m0   = blockIdx.y * 128;
    const int n0   = blockIdx.x * 64;

    // loader coords (p-th chunk): rowX = (tid>>3)+p*32, col = (tid&7)*4
    const int lrow = tid >> 3;
    const int lcs  = (tid & 7) * 4;
    const float* xb = x + (size_t)(m0 + lrow) * DD + lcs;
    const float* wb = w + (size_t)(n0 + lrow) * DD + lcs;

    float acc[2][4][4] = {};
    float4 abuf[4], wbuf[2];

    // prologue: fetch k0 = 0
#pragma unroll
    for (int p = 0; p < 4; p++) abuf[p] = *(const float4*)(xb + (size_t)p * 32 * DD);
#pragma unroll
    for (int p = 0; p < 2; p++) wbuf[p] = *(const float4*)(wb + (size_t)p * 32 * DD);
#pragma unroll
    for (int p = 0; p < 4; p++)
        *(uint4*)&As[lrow + p * 32][lcs] = make_uint4(f2tf32(abuf[p].x), f2tf32(abuf[p].y),
                                                      f2tf32(abuf[p].z), f2tf32(abuf[p].w));
#pragma unroll
    for (int p = 0; p < 2; p++)
        *(uint4*)&Ws[lrow + p * 32][lcs] = make_uint4(f2tf32(wbuf[p].x), f2tf32(wbuf[p].y),
                                                      f2tf32(wbuf[p].z), f2tf32(wbuf[p].w));
    __syncthreads();

    for (int k0 = 0; k0 < DD; k0 += 32) {
        const bool more = (k0 + 32 < DD);
        if (more) {   // prefetch next tile into registers; consumed after compute
#pragma unroll
            for (int p = 0; p < 4; p++) abuf[p] = *(const float4*)(xb + (size_t)p * 32 * DD + k0 + 32);
#pragma unroll
            for (int p = 0; p < 2; p++) wbuf[p] = *(const float4*)(wb + (size_t)p * 32 * DD + k0 + 32);
        }

#pragma unroll
        for (int kk = 0; kk < 32; kk += 8) {
            unsigned af[2][4], bf[4][2];
#pragma unroll
            for (int i = 0; i < 2; i++) {
                const int rb = wm * 32 + i * 16;
                af[i][0] = As[rb + g    ][kk + t    ];
                af[i][1] = As[rb + g + 8][kk + t    ];
                af[i][2] = As[rb + g    ][kk + t + 4];
                af[i][3] = As[rb + g + 8][kk + t + 4];
            }
#pragma unroll
            for (int j = 0; j < 4; j++) {
                const int nb = wn * 32 + j * 8;
                bf[j][0] = Ws[nb + g][kk + t    ];
                bf[j][1] = Ws[nb + g][kk + t + 4];
            }
#pragma unroll
            for (int i = 0; i < 2; i++)
#pragma unroll
                for (int j = 0; j < 4; j++)
                    mma_tf32(acc[i][j], af[i], bf[j]);
        }
        __syncthreads();
        if (more) {
#pragma unroll
            for (int p = 0; p < 4; p++)
                *(uint4*)&As[lrow + p * 32][lcs] = make_uint4(f2tf32(abuf[p].x), f2tf32(abuf[p].y),
                                                              f2tf32(abuf[p].z), f2tf32(abuf[p].w));
#pragma unroll
            for (int p = 0; p < 2; p++)
                *(uint4*)&Ws[lrow + p * 32][lcs] = make_uint4(f2tf32(wbuf[p].x), f2tf32(wbuf[p].y),
                                                              f2tf32(wbuf[p].z), f2tf32(wbuf[p].w));
            __syncthreads();
        }
    }

#pragma unroll
    for (int i = 0; i < 2; i++) {
        const int row0 = m0 + wm * 32 + i * 16 + g;
        const int row1 = row0 + 8;
#pragma unroll
        for (int j = 0; j < 4; j++) {
            const int col = n0 + wn * 32 + j * 8 + 2 * t;   // even
            float v00 = acc[i][j][0], v01 = acc[i][j][1];
            float v10 = acc[i][j][2], v11 = acc[i][j][3];
            if (MODE == 0) {
                *(float2*)(outf + (size_t)row0 * DD + col) = make_float2(v00, v01);
                *(float2*)(outf + (size_t)row1 * DD + col) = make_float2(v10, v11);
            } else {
                const int h = col >> 6, d = col & 63;       // d even
                if (MODE == 2) {
                    const float fr = (float)exp2(-(double)d * 0.20762050593046014);
                    float s0, c0, s1, c1;
                    sincosf((float)tp[row0] * fr, &s0, &c0);
                    sincosf((float)tp[row1] * fr, &s1, &c1);
                    const float e0 = v00, o0 = v01, e1 = v10, o1 = v11;
                    v00 = (e0 * c0 - o0 * s0) * scale;
                    v01 = (e0 * s0 + o0 * c0) * scale;
                    v10 = (e1 * c1 - o1 * s1) * scale;
                    v11 = (e1 * s1 + o1 * c1) * scale;
                }
                unsigned ph, pl;
                {
                    const int bb = row0 / SS, s = row0 % SS;
                    const size_t pidx = (((size_t)(bb * HH + h) * SS + s) * DK + d) >> 1;
                    pack_split(ph, pl, v00, v01);
                    ((unsigned*)oh)[pidx] = ph;
                    ((unsigned*)ol)[pidx] = pl;
                }
                {
                    const int bb = row1 / SS, s = row1 % SS;
                    const size_t pidx = (((size_t)(bb * HH + h) * SS + s) * DK + d) >> 1;
                    pack_split(ph, pl, v10, v11);
                    ((unsigned*)oh)[pidx] = ph;
                    ((unsigned*)ol)[pidx] = pl;
                }
            }
        }
    }
}

// ---------------------------------------------------------------------------
// Tensor-core causal flash attention, bf16x3, cp.async double-buffered K/V.
// CTA: 128 q-rows, 256 thr (8 warps x 16 rows). K-tiles of 64.
// ---------------------------------------------------------------------------
__global__ __launch_bounds__(256, 2)
void attn_tc(const ushort_t* __restrict__ Qhg, const ushort_t* __restrict__ Qlg,
             const ushort_t* __restrict__ Khg, const ushort_t* __restrict__ Klg,
             const ushort_t* __restrict__ Vhg, const ushort_t* __restrict__ Vlg,
             float* __restrict__ O)
{
    extern __shared__ ushort_t smem_us[];
    ushort_t* Qh = smem_us;                 // 128*PH
    ushort_t* Ql = Qh + 128 * PH;
    ushort_t* St = Ql + 128 * PH;           // 2 stages x 4 arrays x 64*PH

    const int tid  = threadIdx.x;
    const int lane = tid & 31, wid = tid >> 5;
    const int g = lane >> 2, t = lane & 3;
    const int qt = (int)gridDim.x - 1 - (int)blockIdx.x;  // heavy CTAs first
    const int h = blockIdx.y, b = blockIdx.z;
    const int Q0 = qt * 128;
    const size_t hoff = (size_t)(b * HH + h) * SS * DK;

    const int grp = lane >> 3, li = lane & 7;
    const int a_r = (grp & 1) * 8 + li, a_c = (grp >> 1) * 8;   // A-frag (and V-trans)
    const int b_r = (grp >> 1) * 8 + li, b_c = (grp & 1) * 8;   // B-frag (K)

    const int lrow = tid & 63, lcq = tid >> 6;   // loader coords

    // ---- prologue: Q + KV tile 0 via cp.async (group 0) ----
    {
#pragma unroll
        for (int rr = 0; rr < 128; rr += 64)
#pragma unroll
            for (int cc = 0; cc < 8; cc += 4) {
                const int r = lrow + rr, c8 = (lcq + cc) * 8;
                const size_t gsrc = hoff + (size_t)(Q0 + r) * DK + c8;
                cpa16(su32(&Qh[r * PH + c8]), &Qhg[gsrc]);
                cpa16(su32(&Ql[r * PH + c8]), &Qlg[gsrc]);
            }
        ushort_t* S0 = St;                         // stage 0
#pragma unroll
        for (int cc = 0; cc < 8; cc += 4) {
            const int c8 = (lcq + cc) * 8;
            const size_t gsrc = hoff + (size_t)lrow * DK + c8;
            cpa16(su32(&S0[0 * 64 * PH + lrow * PH + c8]), &Khg[gsrc]);
            cpa16(su32(&S0[1 * 64 * PH + lrow * PH + c8]), &Klg[gsrc]);
            cpa16(su32(&S0[2 * 64 * PH + lrow * PH + c8]), &Vhg[gsrc]);
            cpa16(su32(&S0[3 * 64 * PH + lrow * PH + c8]), &Vlg[gsrc]);
        }
        cpa_commit();
    }

    float o[8][4] = {};
    float m0 = -INFINITY, m1 = -INFINITY, l0 = 0.f, l1 = 0.f;
    const int rminl = wid * 16;
    const int rming = Q0 + rminl;
    const int ktmax = 2 * qt + 1;

    for (int kt = 0; kt <= ktmax; kt++) {
        __syncthreads();                 // stage (kt+1)&1 free of readers
        if (kt < ktmax) {                // stream tile kt+1 into alt stage
            ushort_t* Sn = St + ((kt + 1) & 1) * (4 * 64 * PH);
            const int Cn = (kt + 1) * 64;
#pragma unroll
            for (int cc = 0; cc < 8; cc += 4) {
                const int c8 = (lcq + cc) * 8;
                const size_t gsrc = hoff + (size_t)(Cn + lrow) * DK + c8;
                cpa16(su32(&Sn[0 * 64 * PH + lrow * PH + c8]), &Khg[gsrc]);
                cpa16(su32(&Sn[1 * 64 * PH + lrow * PH + c8]), &Klg[gsrc]);
                cpa16(su32(&Sn[2 * 64 * PH + lrow * PH + c8]), &Vhg[gsrc]);
                cpa16(su32(&Sn[3 * 64 * PH + lrow * PH + c8]), &Vlg[gsrc]);
            }
            cpa_commit();
            cpa_wait<1>();               // tile kt (and Q) landed
        } else {
            cpa_wait<0>();
        }
        __syncthreads();

        const int C0 = kt * 64;
        if (C0 >= rming + 16) continue;  // fully masked for this warp (barriers done)

        ushort_t* Sc = St + (kt & 1) * (4 * 64 * PH);
        ushort_t* Kh = Sc;
        ushort_t* Kl = Sc + 64 * PH;
        ushort_t* Vh = Sc + 2 * 64 * PH;
        ushort_t* Vl = Sc + 3 * 64 * PH;

        // ---- S = Q K^T, bf16x3 ----
        float sc[8][4];
#pragma unroll
        for (int j = 0; j < 8; j++)
#pragma unroll
            for (int e = 0; e < 4; e++) sc[j][e] = 0.f;

#pragma unroll
        for (int ks = 0; ks < 4; ks++) {
            unsigned qh4[4], ql4[4];
            ldsm4(qh4, su32(&Qh[(rminl + a_r) * PH + 16 * ks + a_c]));
            ldsm4(ql4, su32(&Ql[(rminl + a_r) * PH + 16 * ks + a_c]));
#pragma unroll
            for (int np = 0; np < 4; np++) {
                unsigned kh4[4], kl4[4];
                ldsm4(kh4, su32(&Kh[(np * 16 + b_r) * PH + 16 * ks + b_c]));
                ldsm4(kl4, su32(&Kl[(np * 16 + b_r) * PH + 16 * ks + b_c]));
                mma_bf16(sc[2 * np],     qh4, kh4[0], kh4[1]);
                mma_bf16(sc[2 * np],     qh4, kl4[0], kl4[1]);
                mma_bf16(sc[2 * np],     ql4, kh4[0], kh4[1]);
                mma_bf16(sc[2 * np + 1], qh4, kh4[2], kh4[3]);
                mma_bf16(sc[2 * np + 1], qh4, kl4[2], kl4[3]);
                mma_bf16(sc[2 * np + 1], ql4, kh4[2], kh4[3]);
            }
        }

        // ---- causal mask (diag-adjacent tiles only) ----
        if (C0 + 63 > rming) {
            const int r0g = rming + g, r1g = r0g + 8;
#pragma unroll
            for (int j = 0; j < 8; j++) {
                const int cb = C0 + 8 * j + 2 * t;
                if (cb     > r0g) sc[j][0] = -INFINITY;
                if (cb + 1 > r0g) sc[j][1] = -INFINITY;
                if (cb     > r1g) sc[j][2] = -INFINITY;
                if (cb + 1 > r1g) sc[j][3] = -INFINITY;
            }
        }

        // ---- online softmax (log2 domain) ----
        float mx0 = -INFINITY, mx1 = -INFINITY;
#pragma unroll
        for (int j = 0; j < 8; j++) {
            mx0 = fmaxf(mx0, fmaxf(sc[j][0], sc[j][1]));
            mx1 = fmaxf(mx1, fmaxf(sc[j][2], sc[j][3]));
        }
        mx0 = fmaxf(mx0, __shfl_xor_sync(0xffffffffu, mx0, 1));
        mx0 = fmaxf(mx0, __shfl_xor_sync(0xffffffffu, mx0, 2));
        mx1 = fmaxf(mx1, __shfl_xor_sync(0xffffffffu, mx1, 1));
        mx1 = fmaxf(mx1, __shfl_xor_sync(0xffffffffu, mx1, 2));
        const float mn0 = fmaxf(m0, mx0), mn1 = fmaxf(m1, mx1);
        const float cr0 = ex2(m0 - mn0),  cr1 = ex2(m1 - mn1);
        float rs0 = 0.f, rs1 = 0.f;
#pragma unroll
        for (int j = 0; j < 8; j++) {
            sc[j][0] = ex2(sc[j][0] - mn0); rs0 += sc[j][0];
            sc[j][1] = ex2(sc[j][1] - mn0); rs0 += sc[j][1];
            sc[j][2] = ex2(sc[j][2] - mn1); rs1 += sc[j][2];
            sc[j][3] = ex2(sc[j][3] - mn1); rs1 += sc[j][3];
        }
        rs0 += __shfl_xor_sync(0xffffffffu, rs0, 1);
        rs0 += __shfl_xor_sync(0xffffffffu, rs0, 2);
        rs1 += __shfl_xor_sync(0xffffffffu, rs1, 1);
        rs1 += __shfl_xor_sync(0xffffffffu, rs1, 2);
        l0 = l0 * cr0 + rs0; l1 = l1 * cr1 + rs1;
        m0 = mn0; m1 = mn1;
#pragma unroll
        for (int j = 0; j < 8; j++) {
            o[j][0] *= cr0; o[j][1] *= cr0;
            o[j][2] *= cr1; o[j][3] *= cr1;
        }

        // ---- O += P V, bf16x3 (P packed in-register) ----
#pragma unroll
        for (int cs = 0; cs < 4; cs++) {
            unsigned ph4[4], pl4[4];
            pack_split(ph4[0], pl4[0], sc[2 * cs][0],     sc[2 * cs][1]);
            pack_split(ph4[1], pl4[1], sc[2 * cs][2],     sc[2 * cs][3]);
            pack_split(ph4[2], pl4[2], sc[2 * cs + 1][0], sc[2 * cs + 1][1]);
            pack_split(ph4[3], pl4[3], sc[2 * cs + 1][2], sc[2 * cs + 1][3]);
#pragma unroll
            for (int np = 0; np < 4; np++) {
                unsigned vh4[4], vl4[4];
                ldsm4t(vh4, su32(&Vh[(cs * 16 + a_r) * PH + np * 16 + a_c]));
                ldsm4t(vl4, su32(&Vl[(cs * 16 + a_r) * PH + np * 16 + a_c]));
                mma_bf16(o[2 * np],     ph4, vh4[0], vh4[1]);
                mma_bf16(o[2 * np],     ph4, vl4[0], vl4[1]);
                mma_bf16(o[2 * np],     pl4, vh4[0], vh4[1]);
                mma_bf16(o[2 * np + 1], ph4, vh4[2], vh4[3]);
                mma_bf16(o[2 * np + 1], ph4, vl4[2], vl4[3]);
                mma_bf16(o[2 * np + 1], pl4, vh4[2], vh4[3]);
            }
        }
    }

    // ---- epilogue ----
    const float i0 = 1.0f / l0, i1 = 1.0f / l1;
    const int r0g = Q0 + rminl + g, r1g = r0g + 8;
    float* Ob = O + (size_t)b * SS * DD + h * DK;
#pragma unroll
    for (int j = 0; j < 8; j++) {
        const int col = 8 * j + 2 * t;
        *(float2*)(Ob + (size_t)r0g * DD + col) = make_float2(o[j][0] * i0, o[j][1] * i0);
        *(float2*)(Ob + (size_t)r1g * DD + col) = make_float2(o[j][2] * i1, o[j][3] * i1);
    }
}

// ---------------------------------------------------------------------------
extern "C" void kernel_launch(void* const* d_in, const int* in_sizes, int n_in,
                              void* d_out, int out_size)
{
    const float* x  = (const float*)d_in[0];
    const int*   tp = (const int*)  d_in[1];
    const float* wq = (const float*)d_in[2];
    const float* wk = (const float*)d_in[3];
    const float* wv = (const float*)d_in[4];
    const float* wo = (const float*)d_in[5];
    float* out = (float*)d_out;

    ushort_t *qh, *ql, *kh, *kl, *vh, *vl;
    float* attn;
    cudaGetSymbolAddress((void**)&qh, g_qh);
    cudaGetSymbolAddress((void**)&ql, g_ql);
    cudaGetSymbolAddress((void**)&kh, g_kh);
    cudaGetSymbolAddress((void**)&kl, g_kl);
    cudaGetSymbolAddress((void**)&vh, g_vh);
    cudaGetSymbolAddress((void**)&vl, g_vl);
    cudaGetSymbolAddress((void**)&attn, g_attn);

    const dim3 pgrid(DD / 64, M_TOT / 128);   // (16, 32)
    const float qscale = 0.125f * 1.44269504088896340736f;  // 1/sqrt(64) * log2(e)

    proj_tc<2><<<pgrid, 256>>>(x, wq, tp, nullptr, qh, ql, qscale);
    proj_tc<2><<<pgrid, 256>>>(x, wk, tp, nullptr, kh, kl, 1.0f);
    proj_tc<1><<<pgrid, 256>>>(x, wv, tp, nullptr, vh, vl, 1.0f);

    // Q (2x128xPH) + 2 stages x 4 arrays x 64xPH, halves
    const int smem = (2 * 128 + 2 * 4 * 64) * PH * 2;   // 110592 B
    cudaFuncSetAttribute(attn_tc, cudaFuncAttributeMaxDynamicSharedMemorySize, smem);
    attn_tc<<<dim3(SS / 128, HH, BB), 256, smem>>>(qh, ql, kh, kl, vh, vl, attn);

    proj_tc<0><<<pgrid, 256>>>(attn, wo, tp, out, nullptr, nullptr, 1.0f);
}